// round 16
// baseline (speedup 1.0000x reference)
#include <cuda_runtime.h>
#include <cuda_bf16.h>
#include <cuda_fp16.h>
#include <math.h>

#define N_NODES 10000
#define N_EDGES 160000
#define ETOT    170000   // edges + self loops

// ---------------- scratch (static device memory; no allocations) ----------------
__device__ float g_XL [N_NODES*1024];
__device__ float g_XR [N_NODES*1024];
__device__ float g_H1 [N_NODES*1024];
__device__ float g_H2 [N_NODES*128];
__device__ __nv_bfloat16 g_XBF[N_NODES*128];          // x in bf16 (for XR1)
__device__ __nv_bfloat16 g_H1B[N_NODES*1024];         // H1 in bf16 (for XR2)
__device__ __nv_bfloat16 g_H2B[N_NODES*128];          // H2 in bf16 (for XR3)
__device__ __nv_bfloat16 g_EAFP[(size_t)ETOT*32];     // edge_attr, CSR order, bf16
__device__ unsigned g_WeP1[16*1024];                  // We/Wr packed k-pairs bf16x2 [K/2][N]
__device__ unsigned g_WeP2[16*512];
__device__ unsigned g_WeP3[16*128];
__device__ unsigned g_WrP1[64*1024];
__device__ unsigned g_WrP2[512*512];
__device__ unsigned g_WrP3[64*128];
__device__ unsigned char g_EW1[(size_t)ETOT*1024];    // edge transforms (fp8 e4m3, CSR order)
__device__ unsigned char g_EW2[(size_t)ETOT*512];
__device__ unsigned char g_EW3[(size_t)ETOT*128];
__device__ float g_zbias[1024];                       // stays zero (never written)
__device__ float g_ea_mean[32];
__device__ int   g_deg[N_NODES];
__device__ int   g_rowstart[N_NODES+1];
__device__ int   g_cursor[N_NODES];
__device__ int   g_csr_src[ETOT];

// ---------------- fp8 helpers ----------------
__device__ __forceinline__ unsigned short f2e4m3x2(float lo, float hi) {
    unsigned short r;   // a -> upper byte, b -> lower byte
    asm("cvt.rn.satfinite.e4m3x2.f32 %0, %1, %2;" : "=h"(r) : "f"(hi), "f"(lo));
    return r;
}
__device__ __forceinline__ float2 e4m3x2_to_float2(unsigned short v) {
    unsigned f16x2;
    asm("cvt.rn.f16x2.e4m3x2 %0, %1;" : "=r"(f16x2) : "h"(v));
    __half2 h = *reinterpret_cast<__half2*>(&f16x2);
    return __half22float2(h);
}

// ---------------- CSR build + conversions ----------------
__global__ void ea_mean_zero_k(const float* __restrict__ ea) {
    __shared__ float red[256];
    int c = blockIdx.x;           // 0..31
    int t = threadIdx.x;
    for (int i = c*256 + t; i < N_NODES; i += 32*256) g_deg[i] = 0;
    float s = 0.f;
    for (int e = t; e < N_EDGES; e += 256) s += ea[(size_t)e*32 + c];
    red[t] = s;
    __syncthreads();
    for (int off = 128; off > 0; off >>= 1) {
        if (t < off) red[t] += red[t+off];
        __syncthreads();
    }
    if (t == 0) g_ea_mean[c] = red[0] * (1.0f / N_EDGES);
}

__global__ void count_deg_k(const int* __restrict__ ei) {
    int e = blockIdx.x*blockDim.x + threadIdx.x;
    if (e >= ETOT) return;
    int d = (e < N_EDGES) ? ei[N_EDGES + e] : (e - N_EDGES);
    atomicAdd(&g_deg[d], 1);
}

// single block, 1024 threads, warp-shuffle scan
__global__ void scan_deg_k() {
    __shared__ int wsum[32];
    int t = threadIdx.x;
    const int per = 10;
    int base = t*per;
    int loc[per];
    int s = 0;
    #pragma unroll
    for (int i = 0; i < per; i++) {
        int idx = base+i;
        int v = (idx < N_NODES) ? g_deg[idx] : 0;
        loc[i] = v; s += v;
    }
    int lane = t & 31, w = t >> 5;
    int incl = s;
    #pragma unroll
    for (int off = 1; off < 32; off <<= 1) {
        int n = __shfl_up_sync(0xffffffffu, incl, off);
        if (lane >= off) incl += n;
    }
    if (lane == 31) wsum[w] = incl;
    __syncthreads();
    if (w == 0) {
        int v = wsum[lane];
        #pragma unroll
        for (int off = 1; off < 32; off <<= 1) {
            int n = __shfl_up_sync(0xffffffffu, v, off);
            if (lane >= off) v += n;
        }
        wsum[lane] = v;
    }
    __syncthreads();
    int prefix = incl - s + ((w > 0) ? wsum[w-1] : 0);
    #pragma unroll
    for (int i = 0; i < per; i++) {
        int idx = base+i;
        if (idx < N_NODES) {
            g_rowstart[idx] = prefix;
            g_cursor[idx]   = prefix;
            prefix += loc[i];
        }
    }
    if (t == 1023) g_rowstart[N_NODES] = wsum[31];
}

__global__ void scatter_fill_k(const int* __restrict__ ei, const float* __restrict__ ea) {
    int e = blockIdx.x*blockDim.x + threadIdx.x;
    if (e >= ETOT) return;
    int s, d;
    if (e < N_EDGES) { s = ei[e]; d = ei[N_EDGES + e]; }
    else             { s = e - N_EDGES; d = s; }
    int pos = atomicAdd(&g_cursor[d], 1);
    g_csr_src[pos] = s;
    unsigned* dst = (unsigned*)(g_EAFP + (size_t)pos*32);
    const float2* s2 = (e < N_EDGES) ? (const float2*)(ea + (size_t)e*32)
                                     : (const float2*)g_ea_mean;
    #pragma unroll
    for (int i = 0; i < 16; i++) {
        __nv_bfloat162 h = __float22bfloat162_rn(s2[i]);
        dst[i] = *reinterpret_cast<unsigned*>(&h);
    }
}

// pack fp32 [K][N] -> bf16x2 u32 [K/2][N]; grid.y selects matrix
__global__ void pack_k(const float* __restrict__ We1, const float* __restrict__ We2,
                       const float* __restrict__ We3, const float* __restrict__ Wr1,
                       const float* __restrict__ Wr2, const float* __restrict__ Wr3) {
    int y = blockIdx.y;
    const float* src; unsigned* dst; int N, K;
    if      (y == 0) { src = We1; dst = g_WeP1; K = 32;   N = 1024; }
    else if (y == 1) { src = We2; dst = g_WeP2; K = 32;   N = 512;  }
    else if (y == 2) { src = We3; dst = g_WeP3; K = 32;   N = 128;  }
    else if (y == 3) { src = Wr1; dst = g_WrP1; K = 128;  N = 1024; }
    else if (y == 4) { src = Wr2; dst = g_WrP2; K = 1024; N = 512;  }
    else             { src = Wr3; dst = g_WrP3; K = 128;  N = 128;  }
    int tot = (K >> 1)*N;
    for (int idx = blockIdx.x*blockDim.x + threadIdx.x; idx < tot; idx += gridDim.x*blockDim.x) {
        int k2 = idx / N, n = idx % N;
        __nv_bfloat162 h = __floats2bfloat162_rn(src[(2*k2)*N + n], src[(2*k2+1)*N + n]);
        dst[idx] = *reinterpret_cast<unsigned*>(&h);
    }
}

__global__ void xbf_k(const float* __restrict__ x) {
    int i = blockIdx.x*blockDim.x + threadIdx.x;
    if (i >= N_NODES*64) return;
    float2 v = ((const float2*)x)[i];
    __nv_bfloat162 h = __float22bfloat162_rn(v);
    ((unsigned*)g_XBF)[i] = *reinterpret_cast<unsigned*>(&h);
}

// ---------------- batched GEMM: tf32 pipelined (mode 0) / bf16 pipelined (mode 1) ----------------
// outbf: 0 = fp32 C, 2 = fp8 e4m3 C
__device__ __forceinline__ unsigned f2tf(float f) {
    unsigned u;
    asm("cvt.rna.tf32.f32 %0, %1;" : "=r"(u) : "f"(f));
    return u;
}

__device__ __forceinline__ void mma_tf32(float* d, const unsigned* a, const unsigned* b) {
    asm volatile(
        "mma.sync.aligned.m16n8k8.row.col.f32.tf32.tf32.f32 "
        "{%0,%1,%2,%3}, {%4,%5,%6,%7}, {%8,%9}, {%0,%1,%2,%3};\n"
        : "+f"(d[0]), "+f"(d[1]), "+f"(d[2]), "+f"(d[3])
        : "r"(a[0]), "r"(a[1]), "r"(a[2]), "r"(a[3]), "r"(b[0]), "r"(b[1]));
}

__device__ __forceinline__ void mma_bf16(float* d, const unsigned* a, const unsigned* b) {
    asm volatile(
        "mma.sync.aligned.m16n8k16.row.col.f32.bf16.bf16.f32 "
        "{%0,%1,%2,%3}, {%4,%5,%6,%7}, {%8,%9}, {%0,%1,%2,%3};\n"
        : "+f"(d[0]), "+f"(d[1]), "+f"(d[2]), "+f"(d[3])
        : "r"(a[0]), "r"(a[1]), "r"(a[2]), "r"(a[3]), "r"(b[0]), "r"(b[1]));
}

#define STAGES 3
#define APITCH 36
#define BPITCH 136
#define A_STAGE (128*APITCH)
#define B_STAGE (32*BPITCH)
#define GEMM_SMEM (STAGES*(A_STAGE + B_STAGE)*4)   // 107520 bytes
#define BSTG 23040                                  // bf16 stage bytes: 14336 A + 8704 B

struct GJob {
    const float* A; const float* B; const float* bias; void* C;
    int M, N, K, blk_start, outbf, mode;
};
struct GJobs { GJob j[6]; int njobs; };

__global__ __launch_bounds__(256, 2)
void tf32_gemm_multi(GJobs js)
{
    extern __shared__ float sm_[];
    float* Asm = sm_;
    float* Bsm = sm_ + STAGES*A_STAGE;

    int b = blockIdx.x;
    int zi = 0;
    for (int t = 1; t < js.njobs; t++) if (b >= js.j[t].blk_start) zi = t;
    const GJob jb = js.j[zi];
    const int M = jb.M, N = jb.N;
    int local = b - jb.blk_start;
    int ncols = N >> 7;
    int row0 = (local / ncols)*128;
    int col0 = (local % ncols)*128;

    int tid  = threadIdx.x;
    int warp = tid >> 5, lane = tid & 31;
    int wm = warp >> 2, wn = warp & 3;
    int qr = lane >> 2, qc = lane & 3;

    float acc[4][4][4];
    #pragma unroll
    for (int i = 0; i < 4; i++)
        #pragma unroll
        for (int j = 0; j < 4; j++)
            #pragma unroll
            for (int v = 0; v < 4; v++) acc[i][j][v] = 0.f;

    if (jb.mode == 1) {
        // ---- bf16 pipelined path: A bf16 [M][K] row-major, B packed u32 [K/2][N] ----
        const __nv_bfloat16* Ab = (const __nv_bfloat16*)jb.A;
        const unsigned* Bp = (const unsigned*)jb.B;
        const int K = jb.K;
        int nt = K >> 5;
        char* smb = (char*)sm_;

        auto issue_bf = [&](int kt) {
            int s  = kt % STAGES;
            int k0 = kt << 5;
            char* As = smb + s*BSTG;
            char* Bs = smb + s*BSTG + 14336;
            #pragma unroll
            for (int it = 0; it < 2; it++) {
                int id  = tid + it*256;
                int row = id >> 2, kc = id & 3;
                const void* src = Ab + (size_t)(row0+row)*K + k0 + kc*8;
                unsigned dst = (unsigned)__cvta_generic_to_shared(As + row*112 + kc*16);
                int sz = (row0+row < M) ? 16 : 0;
                asm volatile("cp.async.cg.shared.global [%0], [%1], 16, %2;\n"
                             :: "r"(dst), "l"(src), "r"(sz));
            }
            #pragma unroll
            for (int it = 0; it < 2; it++) {
                int id = tid + it*256;
                int k2l = id >> 5, nc = (id & 31)*4;
                const unsigned* src = Bp + (size_t)((k0 >> 1) + k2l)*N + col0 + nc;
                unsigned dst = (unsigned)__cvta_generic_to_shared(Bs + (k2l*136 + nc)*4);
                asm volatile("cp.async.cg.shared.global [%0], [%1], 16, 16;\n"
                             :: "r"(dst), "l"(src));
            }
            asm volatile("cp.async.commit_group;\n");
        };

        auto compute_bf = [&](int s) {
            const char* As = smb + s*BSTG;
            const unsigned* Bs = (const unsigned*)(smb + s*BSTG + 14336);
            #pragma unroll
            for (int ks = 0; ks < 2; ks++) {
                unsigned a[4][4], bfr[4][2];
                #pragma unroll
                for (int mt = 0; mt < 4; mt++) {
                    int m_ = wm*64 + mt*16 + qr;
                    a[mt][0] = *(const unsigned*)(As + m_    *112 + (qc   + ks*8)*4);
                    a[mt][1] = *(const unsigned*)(As + (m_+8)*112 + (qc   + ks*8)*4);
                    a[mt][2] = *(const unsigned*)(As + m_    *112 + (qc+4 + ks*8)*4);
                    a[mt][3] = *(const unsigned*)(As + (m_+8)*112 + (qc+4 + ks*8)*4);
                }
                #pragma unroll
                for (int nt_ = 0; nt_ < 4; nt_++) {
                    int n_ = wn*32 + nt_*8 + qr;
                    bfr[nt_][0] = Bs[(qc   + ks*8)*136 + n_];
                    bfr[nt_][1] = Bs[(qc+4 + ks*8)*136 + n_];
                }
                #pragma unroll
                for (int mt = 0; mt < 4; mt++)
                    #pragma unroll
                    for (int nt_ = 0; nt_ < 4; nt_++)
                        mma_bf16(acc[mt][nt_], a[mt], bfr[nt_]);
            }
        };

        int pre = (nt < STAGES-1) ? nt : (STAGES-1);
        for (int kt = 0; kt < pre; kt++) issue_bf(kt);

        for (int kt = 0; kt < nt; kt++) {
            if (nt - kt - 1 >= 1)
                asm volatile("cp.async.wait_group 1;\n");
            else
                asm volatile("cp.async.wait_group 0;\n");
            __syncthreads();
            compute_bf(kt % STAGES);
            if (kt + STAGES-1 < nt) issue_bf(kt + STAGES-1);
        }
    } else {
        // ---- tf32 cp.async 3-stage pipeline (single sync/iter) ----
        const float* __restrict__ A = jb.A;
        const float* __restrict__ B = jb.B;
        const int K = jb.K;
        int nt = K >> 5;

        auto issue = [&](int kt) {
            int s  = kt % STAGES;
            int k0 = kt << 5;
            float* As = Asm + s*A_STAGE;
            float* Bs = Bsm + s*B_STAGE;
            #pragma unroll
            for (int it = 0; it < 4; it++) {
                int id  = tid + it*256;
                int row = id >> 3;
                int kc  = (id & 7)*4;
                const float* src = A + (size_t)(row0+row)*K + k0 + kc;
                unsigned dst = (unsigned)__cvta_generic_to_shared(As + row*APITCH + kc);
                int sz = (row0+row < M) ? 16 : 0;
                asm volatile("cp.async.cg.shared.global [%0], [%1], 16, %2;\n"
                             :: "r"(dst), "l"(src), "r"(sz));
            }
            #pragma unroll
            for (int it = 0; it < 4; it++) {
                int id = tid + it*256;
                int kr = id >> 5;
                int nc = (id & 31)*4;
                const float* src = B + (size_t)(k0+kr)*N + col0 + nc;
                unsigned dst = (unsigned)__cvta_generic_to_shared(Bs + kr*BPITCH + nc);
                asm volatile("cp.async.cg.shared.global [%0], [%1], 16, 16;\n"
                             :: "r"(dst), "l"(src));
            }
            asm volatile("cp.async.commit_group;\n");
        };

        auto compute = [&](int s) {
            const float* As = Asm + s*A_STAGE;
            const float* Bs = Bsm + s*B_STAGE;
            #pragma unroll
            for (int ks = 0; ks < 4; ks++) {
                int kb = ks*8;
                unsigned a[4][4], bfr[4][2];
                #pragma unroll
                for (int mt = 0; mt < 4; mt++) {
                    int m_ = wm*64 + mt*16 + qr;
                    a[mt][0] = f2tf(As[(size_t)m_     *APITCH + kb+qc  ]);
                    a[mt][1] = f2tf(As[(size_t)(m_+8) *APITCH + kb+qc  ]);
                    a[mt][2] = f2tf(As[(size_t)m_     *APITCH + kb+qc+4]);
                    a[mt][3] = f2tf(As[(size_t)(m_+8) *APITCH + kb+qc+4]);
                }
                #pragma unroll
                for (int nt_ = 0; nt_ < 4; nt_++) {
                    int n_ = wn*32 + nt_*8 + qr;
                    bfr[nt_][0] = f2tf(Bs[(size_t)(kb+qc  )*BPITCH + n_]);
                    bfr[nt_][1] = f2tf(Bs[(size_t)(kb+qc+4)*BPITCH + n_]);
                }
                #pragma unroll
                for (int mt = 0; mt < 4; mt++)
                    #pragma unroll
                    for (int nt_ = 0; nt_ < 4; nt_++)
                        mma_tf32(acc[mt][nt_], a[mt], bfr[nt_]);
            }
        };

        int pre = (nt < STAGES-1) ? nt : (STAGES-1);
        for (int kt = 0; kt < pre; kt++) issue(kt);

        for (int kt = 0; kt < nt; kt++) {
            if (nt - kt - 1 >= 1)
                asm volatile("cp.async.wait_group 1;\n");
            else
                asm volatile("cp.async.wait_group 0;\n");
            __syncthreads();
            compute(kt % STAGES);
            if (kt + STAGES-1 < nt) issue(kt + STAGES-1);
        }
    }

    // ---- common epilogue ----
    const float* bias = jb.bias;
    #pragma unroll
    for (int mt = 0; mt < 4; mt++) {
        int r  = row0 + wm*64 + mt*16 + qr;
        int r2 = r + 8;
        #pragma unroll
        for (int nt_ = 0; nt_ < 4; nt_++) {
            int c = col0 + wn*32 + nt_*8 + qc*2;
            float b0 = bias[c], b1 = bias[c+1];
            if (jb.outbf == 2) {
                unsigned char* C8 = (unsigned char*)jb.C;
                if (r  < M) {
                    unsigned short v = f2e4m3x2(acc[mt][nt_][0] + b0, acc[mt][nt_][1] + b1);
                    asm volatile("st.global.cs.u16 [%0], %1;\n"
                                 :: "l"(C8 + (size_t)r*N + c), "h"(v));
                }
                if (r2 < M) {
                    unsigned short v = f2e4m3x2(acc[mt][nt_][2] + b0, acc[mt][nt_][3] + b1);
                    asm volatile("st.global.cs.u16 [%0], %1;\n"
                                 :: "l"(C8 + (size_t)r2*N + c), "h"(v));
                }
            } else {
                float* C = (float*)jb.C;
                if (r  < M) {
                    C[(size_t)r *N + c]   = acc[mt][nt_][0] + b0;
                    C[(size_t)r *N + c+1] = acc[mt][nt_][1] + b1;
                }
                if (r2 < M) {
                    C[(size_t)r2*N + c]   = acc[mt][nt_][2] + b0;
                    C[(size_t)r2*N + c+1] = acc[mt][nt_][3] + b1;
                }
            }
        }
    }
}

// ---------------- fused GATv2 aggregation: one warp per (node, head) ----------------
// EW stored fp8 e4m3 in CSR order.
// EPI: 0 = layer 2: block merge of 4 heads (mean) + bias + ELU -> g_H2 (+bf16 copy)
//      1 = +bias +residual(g_H1) +leaky_relu, write g_H1 (+bf16 copy)
//      2 = layer 3 (H=1): +bias +ELU, then FUSED classifier head -> out
template<int D, int H, int EPI>
__global__ __launch_bounds__(256)
void gat_node(const unsigned char* __restrict__ EW, const float* __restrict__ att,
              const float* __restrict__ bo,
              const float* __restrict__ Wc1, const float* __restrict__ bc1,
              const float* __restrict__ Wc2, const float* __restrict__ bc2,
              float* __restrict__ out)
{
    int warp = (blockIdx.x*blockDim.x + threadIdx.x) >> 5;
    int lane = threadIdx.x & 31;
    if (warp >= N_NODES*H) return;
    int d = warp / H, h = warp % H;
    const int cbase = h*128 + lane*4;

    float4 a4 = *(const float4*)(att + h*128 + lane*4);
    float4 xr = *(const float4*)(g_XR + (size_t)d*D + cbase);

    float m0 = -INFINITY, z0 = 0.f, A00 = 0.f, A01 = 0.f, A02 = 0.f, A03 = 0.f;
    float m1 = -INFINITY, z1 = 0.f, A10 = 0.f, A11 = 0.f, A12 = 0.f, A13 = 0.f;

    int start = g_rowstart[d], end = g_rowstart[d+1];
    int pos = start;

    for (; pos + 2 <= end; pos += 2) {
        int sa = g_csr_src[pos];
        int sb = g_csr_src[pos+1];
        unsigned ra = __ldcs((const unsigned*)(EW + (size_t)pos    *D + cbase));
        unsigned rb = __ldcs((const unsigned*)(EW + (size_t)(pos+1)*D + cbase));
        float4 xla = *(const float4*)(g_XL + (size_t)sa*D + cbase);
        float4 xlb = *(const float4*)(g_XL + (size_t)sb*D + cbase);

        float2 wa01 = e4m3x2_to_float2((unsigned short)(ra & 0xffffu));
        float2 wa23 = e4m3x2_to_float2((unsigned short)(ra >> 16));
        float2 wb01 = e4m3x2_to_float2((unsigned short)(rb & 0xffffu));
        float2 wb23 = e4m3x2_to_float2((unsigned short)(rb >> 16));

        float qa0 = xla.x + xr.x + wa01.x;
        float qa1 = xla.y + xr.y + wa01.y;
        float qa2 = xla.z + xr.z + wa23.x;
        float qa3 = xla.w + xr.w + wa23.y;
        float qb0 = xlb.x + xr.x + wb01.x;
        float qb1 = xlb.y + xr.y + wb01.y;
        float qb2 = xlb.z + xr.z + wb23.x;
        float qb3 = xlb.w + xr.w + wb23.y;
        qa0 = (qa0 > 0.f) ? qa0 : 0.2f*qa0;
        qa1 = (qa1 > 0.f) ? qa1 : 0.2f*qa1;
        qa2 = (qa2 > 0.f) ? qa2 : 0.2f*qa2;
        qa3 = (qa3 > 0.f) ? qa3 : 0.2f*qa3;
        qb0 = (qb0 > 0.f) ? qb0 : 0.2f*qb0;
        qb1 = (qb1 > 0.f) ? qb1 : 0.2f*qb1;
        qb2 = (qb2 > 0.f) ? qb2 : 0.2f*qb2;
        qb3 = (qb3 > 0.f) ? qb3 : 0.2f*qb3;

        float pa = a4.x*qa0 + a4.y*qa1 + a4.z*qa2 + a4.w*qa3;
        float pb = a4.x*qb0 + a4.y*qb1 + a4.z*qb2 + a4.w*qb3;
        #pragma unroll
        for (int off = 16; off > 0; off >>= 1) {
            pa += __shfl_xor_sync(0xffffffffu, pa, off);
            pb += __shfl_xor_sync(0xffffffffu, pb, off);
        }

        float nm0 = fmaxf(m0, pa);
        float sc0 = __expf(m0 - nm0);
        float w0  = __expf(pa - nm0);
        z0  = z0*sc0 + w0;
        A00 = A00*sc0 + w0*xla.x;
        A01 = A01*sc0 + w0*xla.y;
        A02 = A02*sc0 + w0*xla.z;
        A03 = A03*sc0 + w0*xla.w;
        m0 = nm0;

        float nm1 = fmaxf(m1, pb);
        float sc1 = __expf(m1 - nm1);
        float w1  = __expf(pb - nm1);
        z1  = z1*sc1 + w1;
        A10 = A10*sc1 + w1*xlb.x;
        A11 = A11*sc1 + w1*xlb.y;
        A12 = A12*sc1 + w1*xlb.z;
        A13 = A13*sc1 + w1*xlb.w;
        m1 = nm1;
    }

    if (pos < end) {
        int s_ = g_csr_src[pos];
        unsigned r_ = __ldcs((const unsigned*)(EW + (size_t)pos*D + cbase));
        float4 xl = *(const float4*)(g_XL + (size_t)s_*D + cbase);
        float2 w01 = e4m3x2_to_float2((unsigned short)(r_ & 0xffffu));
        float2 w23 = e4m3x2_to_float2((unsigned short)(r_ >> 16));
        float q0 = xl.x + xr.x + w01.x;
        float q1 = xl.y + xr.y + w01.y;
        float q2 = xl.z + xr.z + w23.x;
        float q3 = xl.w + xr.w + w23.y;
        q0 = (q0 > 0.f) ? q0 : 0.2f*q0;
        q1 = (q1 > 0.f) ? q1 : 0.2f*q1;
        q2 = (q2 > 0.f) ? q2 : 0.2f*q2;
        q3 = (q3 > 0.f) ? q3 : 0.2f*q3;
        float p = a4.x*q0 + a4.y*q1 + a4.z*q2 + a4.w*q3;
        #pragma unroll
        for (int off = 16; off > 0; off >>= 1)
            p += __shfl_xor_sync(0xffffffffu, p, off);
        float nm0 = fmaxf(m0, p);
        float sc0 = __expf(m0 - nm0);
        float w0  = __expf(p - nm0);
        z0  = z0*sc0 + w0;
        A00 = A00*sc0 + w0*xl.x;
        A01 = A01*sc0 + w0*xl.y;
        A02 = A02*sc0 + w0*xl.z;
        A03 = A03*sc0 + w0*xl.w;
        m0 = nm0;
    }

    float M_ = fmaxf(m0, m1);
    float s0 = __expf(m0 - M_);
    float s1 = __expf(m1 - M_);
    float z  = z0*s0 + z1*s1;
    float o0 = A00*s0 + A10*s1;
    float o1 = A01*s0 + A11*s1;
    float o2 = A02*s0 + A12*s1;
    float o3 = A03*s0 + A13*s1;

    float inv = 1.0f / (z + 1e-16f);
    o0 *= inv; o1 *= inv; o2 *= inv; o3 *= inv;

    if (EPI == 0) {
        __shared__ float sm[8][132];
        int wid = threadIdx.x >> 5;
        sm[wid][lane*4+0] = o0;
        sm[wid][lane*4+1] = o1;
        sm[wid][lane*4+2] = o2;
        sm[wid][lane*4+3] = o3;
        __syncthreads();
        int t = threadIdx.x;
        int slot = t >> 7, c = t & 127;
        int dd = blockIdx.x*2 + slot;
        float v = 0.25f*(sm[slot*4+0][c] + sm[slot*4+1][c] +
                         sm[slot*4+2][c] + sm[slot*4+3][c]) + bo[c];
        v = (v > 0.f) ? v : expm1f(v);
        g_H2[dd*128 + c]  = v;
        g_H2B[dd*128 + c] = __float2bfloat16_rn(v);
    } else if (EPI == 1) {
        float4 b4  = *(const float4*)(bo + cbase);
        float4 res = *(const float4*)(g_H1 + (size_t)d*1024 + cbase);
        float v0 = o0 + b4.x + res.x;
        float v1 = o1 + b4.y + res.y;
        float v2 = o2 + b4.z + res.z;
        float v3 = o3 + b4.w + res.w;
        v0 = (v0 > 0.f) ? v0 : 0.2f*v0;
        v1 = (v1 > 0.f) ? v1 : 0.2f*v1;
        v2 = (v2 > 0.f) ? v2 : 0.2f*v2;
        v3 = (v3 > 0.f) ? v3 : 0.2f*v3;
        *(float4*)(g_H1 + (size_t)d*1024 + cbase) = make_float4(v0, v1, v2, v3);
        __nv_bfloat162 h01 = __floats2bfloat162_rn(v0, v1);
        __nv_bfloat162 h23 = __floats2bfloat162_rn(v2, v3);
        uint2 u = make_uint2(*reinterpret_cast<unsigned*>(&h01),
                             *reinterpret_cast<unsigned*>(&h23));
        *(uint2*)(g_H1B + (size_t)d*1024 + cbase) = u;
    } else {
        __shared__ float sh3[8][132];
        __shared__ float shc[8][64];
        float4 b4 = *(const float4*)(bo + cbase);
        float v0 = o0 + b4.x;
        float v1 = o1 + b4.y;
        float v2 = o2 + b4.z;
        float v3 = o3 + b4.w;
        v0 = (v0 > 0.f) ? v0 : expm1f(v0);
        v1 = (v1 > 0.f) ? v1 : expm1f(v1);
        v2 = (v2 > 0.f) ? v2 : expm1f(v2);
        v3 = (v3 > 0.f) ? v3 : expm1f(v3);
        int wid = threadIdx.x >> 5;
        sh3[wid][lane*4+0] = v0;
        sh3[wid][lane*4+1] = v1;
        sh3[wid][lane*4+2] = v2;
        sh3[wid][lane*4+3] = v3;
        __syncthreads();
        {
            int nd = wid;
            int j0 = lane*2;
            float t0 = bc1[j0], t1 = bc1[j0+1];
            #pragma unroll 4
            for (int c = 0; c < 128; c++) {
                float hv = sh3[nd][c];
                t0 = fmaf(hv, Wc1[c*64 + j0],     t0);
                t1 = fmaf(hv, Wc1[c*64 + j0 + 1], t1);
            }
            t0 = (t0 > 0.f) ? t0 : expm1f(t0);
            t1 = (t1 > 0.f) ? t1 : expm1f(t1);
            shc[nd][j0]   = t0;
            shc[nd][j0+1] = t1;
        }
        __syncthreads();
        if (lane < 3) {
            int nd = wid;
            float s = bc2[lane];
            #pragma unroll 8
            for (int k = 0; k < 64; k++)
                s = fmaf(shc[nd][k], Wc2[k*3 + lane], s);
            out[(blockIdx.x*8 + nd)*3 + lane] = s;
        }
    }
}

// ---------------- launch ----------------
extern "C" void kernel_launch(void* const* d_in, const int* in_sizes, int n_in,
                              void* d_out, int out_size)
{
    const float* x    = (const float*)d_in[0];
    const int*   ei   = (const int*)  d_in[1];
    const float* ea   = (const float*)d_in[2];
    const float* Wl1  = (const float*)d_in[3];
    const float* bl1  = (const float*)d_in[4];
    const float* Wr1  = (const float*)d_in[5];
    const float* br1  = (const float*)d_in[6];
    const float* We1  = (const float*)d_in[7];
    const float* att1 = (const float*)d_in[8];
    const float* bo1  = (const float*)d_in[9];
    const float* Wl2  = (const float*)d_in[10];
    const float* bl2  = (const float*)d_in[11];
    const float* Wr2  = (const float*)d_in[12];
    const float* br2  = (const float*)d_in[13];
    const float* We2  = (const float*)d_in[14];
    const float* att2 = (const float*)d_in[15];
    const float* bo2  = (const float*)d_in[16];
    const float* Wl3  = (const float*)d_in[17];
    const float* bl3  = (const float*)d_in[18];
    const float* Wr3  = (const float*)d_in[19];
    const float* br3  = (const float*)d_in[20];
    const float* We3  = (const float*)d_in[21];
    const float* att3 = (const float*)d_in[22];
    const float* bo3  = (const float*)d_in[23];
    const float* Wres = (const float*)d_in[24];
    const float* bres = (const float*)d_in[25];
    const float* Wc1  = (const float*)d_in[26];
    const float* bc1  = (const float*)d_in[27];
    const float* Wc2  = (const float*)d_in[28];
    const float* bc2  = (const float*)d_in[29];
    float* out = (float*)d_out;

    void *pXL, *pXR, *pH1, *pH2, *pXBF, *pH1B, *pH2B, *pEAFP, *pZB;
    void *pWeP1, *pWeP2, *pWeP3, *pWrP1, *pWrP2, *pWrP3, *pEW1, *pEW2, *pEW3;
    cudaGetSymbolAddress(&pXL,   g_XL);
    cudaGetSymbolAddress(&pXR,   g_XR);
    cudaGetSymbolAddress(&pH1,   g_H1);
    cudaGetSymbolAddress(&pH2,   g_H2);
    cudaGetSymbolAddress(&pXBF,  g_XBF);
    cudaGetSymbolAddress(&pH1B,  g_H1B);
    cudaGetSymbolAddress(&pH2B,  g_H2B);
    cudaGetSymbolAddress(&pEAFP, g_EAFP);
    cudaGetSymbolAddress(&pWeP1, g_WeP1);
    cudaGetSymbolAddress(&pWeP2, g_WeP2);
    cudaGetSymbolAddress(&pWeP3, g_WeP3);
    cudaGetSymbolAddress(&pWrP1, g_WrP1);
    cudaGetSymbolAddress(&pWrP2, g_WrP2);
    cudaGetSymbolAddress(&pWrP3, g_WrP3);
    cudaGetSymbolAddress(&pEW1,  g_EW1);
    cudaGetSymbolAddress(&pEW2,  g_EW2);
    cudaGetSymbolAddress(&pEW3,  g_EW3);
    cudaGetSymbolAddress(&pZB,   g_zbias);

    cudaFuncSetAttribute(tf32_gemm_multi, cudaFuncAttributeMaxDynamicSharedMemorySize, GEMM_SMEM);

    // graph structure + conversions (rebuilt every call: deterministic work)
    ea_mean_zero_k<<<32, 256>>>(ea);
    pack_k<<<dim3(256, 6), 256>>>(We1, We2, We3, Wr1, Wr2, Wr3);
    xbf_k<<<(N_NODES*64 + 255)/256, 256>>>(x);
    count_deg_k<<<(ETOT+255)/256, 256>>>(ei);
    scan_deg_k<<<1, 1024>>>();
    scatter_fill_k<<<(ETOT+255)/256, 256>>>(ei, ea);

    const int MT = (N_NODES + 127)/128;   // 79
    const int ET = (ETOT + 127)/128;      // 1329

    // ---- mega-launch: XL1/RES (tf32) + XR1 (bf16) + EW1/2/3 (bf16 mma, fp8 out) ----
    {
        GJobs js;
        const float* eaf = (const float*)pEAFP;
        const float* zb  = (const float*)pZB;
        js.j[0] = { x,                   Wl1,  bl1,  pXL,  N_NODES, 1024, 128, 0,      0, 0 };
        js.j[1] = { x,                   Wres, bres, pH1,  N_NODES, 1024, 128, MT*8,   0, 0 };
        js.j[2] = { (const float*)pXBF,  (const float*)pWrP1, br1, pXR, N_NODES, 1024, 128, 2*MT*8, 0, 1 };
        js.j[3] = { eaf, (const float*)pWeP1, zb, pEW1, ETOT, 1024, 32, 3*MT*8,          2, 1 };
        js.j[4] = { eaf, (const float*)pWeP2, zb, pEW2, ETOT, 512,  32, 3*MT*8 + ET*8,   2, 1 };
        js.j[5] = { eaf, (const float*)pWeP3, zb, pEW3, ETOT, 128,  32, 3*MT*8 + ET*12,  2, 1 };
        js.njobs = 6;
        int nblk = 3*MT*8 + ET*13;
        tf32_gemm_multi<<<nblk, 256, GEMM_SMEM>>>(js);
    }
    gat_node<1024,8,1><<<(N_NODES*8*32)/256, 256>>>((const unsigned char*)pEW1, att1, bo1,
                                                    nullptr, nullptr, nullptr, nullptr, nullptr);

    // ---- layer 2: XL (tf32, fp32 H1) + XR (bf16, H1B) ----
    {
        GJobs js;
        js.j[0] = { (const float*)pH1,  Wl2, bl2, pXL, N_NODES, 512, 1024, 0,    0, 0 };
        js.j[1] = { (const float*)pH1B, (const float*)pWrP2, br2, pXR, N_NODES, 512, 1024, MT*4, 0, 1 };
        js.j[2] = js.j[1]; js.j[3] = js.j[1]; js.j[4] = js.j[1]; js.j[5] = js.j[1];
        js.njobs = 2;
        tf32_gemm_multi<<<2*MT*4, 256, GEMM_SMEM>>>(js);
    }
    gat_node<512,4,0><<<(N_NODES*4*32)/256, 256>>>((const unsigned char*)pEW2, att2, bo2,
                                                   nullptr, nullptr, nullptr, nullptr, nullptr);

    // ---- layer 3: XL (tf32) + XR (bf16) ----
    {
        GJobs js;
        js.j[0] = { (const float*)pH2,  Wl3, bl3, pXL, N_NODES, 128, 128, 0,  0, 0 };
        js.j[1] = { (const float*)pH2B, (const float*)pWrP3, br3, pXR, N_NODES, 128, 128, MT, 0, 1 };
        js.j[2] = js.j[1]; js.j[3] = js.j[1]; js.j[4] = js.j[1]; js.j[5] = js.j[1];
        js.njobs = 2;
        tf32_gemm_multi<<<2*MT, 256, GEMM_SMEM>>>(js);
    }
    gat_node<128,1,2><<<(N_NODES*1*32)/256, 256>>>((const unsigned char*)pEW3, att3, bo3,
                                                   Wc1, bc1, Wc2, bc2, out);
}

// round 17
// speedup vs baseline: 1.0264x; 1.0264x over previous
#include <cuda_runtime.h>
#include <cuda_bf16.h>
#include <math.h>

#define N_NODES 10000
#define N_EDGES 160000
#define ETOT    170000   // edges + self loops

// ---------------- scratch (static device memory; no allocations) ----------------
__device__ float g_XL [N_NODES*1024];
__device__ float g_XR [N_NODES*1024];
__device__ float g_H1 [N_NODES*1024];
__device__ float g_H2 [N_NODES*128];
__device__ __nv_bfloat16 g_XBF[N_NODES*128];          // x in bf16 (for XR1)
__device__ __nv_bfloat16 g_H1B[N_NODES*1024];         // H1 in bf16 (for XR2)
__device__ __nv_bfloat16 g_H2B[N_NODES*128];          // H2 in bf16 (for XR3)
__device__ __nv_bfloat16 g_EAFP[(size_t)ETOT*32];     // edge_attr, CSR order, bf16
__device__ unsigned g_WeP1[16*1024];                  // We/Wr packed k-pairs bf16x2 [K/2][N]
__device__ unsigned g_WeP2[16*512];
__device__ unsigned g_WeP3[16*128];
__device__ unsigned g_WrP1[64*1024];
__device__ unsigned g_WrP2[512*512];
__device__ unsigned g_WrP3[64*128];
__device__ __nv_bfloat16 g_EW1[(size_t)ETOT*1024];    // edge transforms (bf16, CSR order)
__device__ __nv_bfloat16 g_EW2[(size_t)ETOT*512];
__device__ __nv_bfloat16 g_EW3[(size_t)ETOT*128];
__device__ float g_zbias[1024];                       // stays zero (never written)
__device__ float g_ea_mean[32];
__device__ int   g_deg[N_NODES];
__device__ int   g_rowstart[N_NODES+1];
__device__ int   g_cursor[N_NODES];
__device__ int   g_csr_src[ETOT];

// ---------------- CSR build + conversions ----------------
__global__ void ea_mean_zero_k(const float* __restrict__ ea) {
    __shared__ float red[256];
    int c = blockIdx.x;           // 0..31
    int t = threadIdx.x;
    for (int i = c*256 + t; i < N_NODES; i += 32*256) g_deg[i] = 0;
    float s = 0.f;
    for (int e = t; e < N_EDGES; e += 256) s += ea[(size_t)e*32 + c];
    red[t] = s;
    __syncthreads();
    for (int off = 128; off > 0; off >>= 1) {
        if (t < off) red[t] += red[t+off];
        __syncthreads();
    }
    if (t == 0) g_ea_mean[c] = red[0] * (1.0f / N_EDGES);
}

__global__ void count_deg_k(const int* __restrict__ ei) {
    int e = blockIdx.x*blockDim.x + threadIdx.x;
    if (e >= ETOT) return;
    int d = (e < N_EDGES) ? ei[N_EDGES + e] : (e - N_EDGES);
    atomicAdd(&g_deg[d], 1);
}

// single block, 1024 threads, warp-shuffle scan
__global__ void scan_deg_k() {
    __shared__ int wsum[32];
    int t = threadIdx.x;
    const int per = 10;
    int base = t*per;
    int loc[per];
    int s = 0;
    #pragma unroll
    for (int i = 0; i < per; i++) {
        int idx = base+i;
        int v = (idx < N_NODES) ? g_deg[idx] : 0;
        loc[i] = v; s += v;
    }
    int lane = t & 31, w = t >> 5;
    int incl = s;
    #pragma unroll
    for (int off = 1; off < 32; off <<= 1) {
        int n = __shfl_up_sync(0xffffffffu, incl, off);
        if (lane >= off) incl += n;
    }
    if (lane == 31) wsum[w] = incl;
    __syncthreads();
    if (w == 0) {
        int v = wsum[lane];
        #pragma unroll
        for (int off = 1; off < 32; off <<= 1) {
            int n = __shfl_up_sync(0xffffffffu, v, off);
            if (lane >= off) v += n;
        }
        wsum[lane] = v;
    }
    __syncthreads();
    int prefix = incl - s + ((w > 0) ? wsum[w-1] : 0);
    #pragma unroll
    for (int i = 0; i < per; i++) {
        int idx = base+i;
        if (idx < N_NODES) {
            g_rowstart[idx] = prefix;
            g_cursor[idx]   = prefix;
            prefix += loc[i];
        }
    }
    if (t == 1023) g_rowstart[N_NODES] = wsum[31];
}

__global__ void scatter_fill_k(const int* __restrict__ ei, const float* __restrict__ ea) {
    int e = blockIdx.x*blockDim.x + threadIdx.x;
    if (e >= ETOT) return;
    int s, d;
    if (e < N_EDGES) { s = ei[e]; d = ei[N_EDGES + e]; }
    else             { s = e - N_EDGES; d = s; }
    int pos = atomicAdd(&g_cursor[d], 1);
    g_csr_src[pos] = s;
    unsigned* dst = (unsigned*)(g_EAFP + (size_t)pos*32);
    const float2* s2 = (e < N_EDGES) ? (const float2*)(ea + (size_t)e*32)
                                     : (const float2*)g_ea_mean;
    #pragma unroll
    for (int i = 0; i < 16; i++) {
        __nv_bfloat162 h = __float22bfloat162_rn(s2[i]);
        dst[i] = *reinterpret_cast<unsigned*>(&h);
    }
}

// pack fp32 [K][N] -> bf16x2 u32 [K/2][N]; grid.y selects matrix; y==6 converts x
__global__ void pack_k(const float* __restrict__ We1, const float* __restrict__ We2,
                       const float* __restrict__ We3, const float* __restrict__ Wr1,
                       const float* __restrict__ Wr2, const float* __restrict__ Wr3,
                       const float* __restrict__ x) {
    int y = blockIdx.y;
    if (y == 6) {
        for (int i = blockIdx.x*blockDim.x + threadIdx.x; i < N_NODES*64;
             i += gridDim.x*blockDim.x) {
            float2 v = ((const float2*)x)[i];
            __nv_bfloat162 h = __float22bfloat162_rn(v);
            ((unsigned*)g_XBF)[i] = *reinterpret_cast<unsigned*>(&h);
        }
        return;
    }
    const float* src; unsigned* dst; int N, K;
    if      (y == 0) { src = We1; dst = g_WeP1; K = 32;   N = 1024; }
    else if (y == 1) { src = We2; dst = g_WeP2; K = 32;   N = 512;  }
    else if (y == 2) { src = We3; dst = g_WeP3; K = 32;   N = 128;  }
    else if (y == 3) { src = Wr1; dst = g_WrP1; K = 128;  N = 1024; }
    else if (y == 4) { src = Wr2; dst = g_WrP2; K = 1024; N = 512;  }
    else             { src = Wr3; dst = g_WrP3; K = 128;  N = 128;  }
    int tot = (K >> 1)*N;
    for (int idx = blockIdx.x*blockDim.x + threadIdx.x; idx < tot; idx += gridDim.x*blockDim.x) {
        int k2 = idx / N, n = idx % N;
        __nv_bfloat162 h = __floats2bfloat162_rn(src[(2*k2)*N + n], src[(2*k2+1)*N + n]);
        dst[idx] = *reinterpret_cast<unsigned*>(&h);
    }
}

// ---------------- batched GEMM: tf32 pipelined (mode 0) / bf16 pipelined (mode 1) ----------------
__device__ __forceinline__ unsigned f2tf(float f) {
    unsigned u;
    asm("cvt.rna.tf32.f32 %0, %1;" : "=r"(u) : "f"(f));
    return u;
}

__device__ __forceinline__ void mma_tf32(float* d, const unsigned* a, const unsigned* b) {
    asm volatile(
        "mma.sync.aligned.m16n8k8.row.col.f32.tf32.tf32.f32 "
        "{%0,%1,%2,%3}, {%4,%5,%6,%7}, {%8,%9}, {%0,%1,%2,%3};\n"
        : "+f"(d[0]), "+f"(d[1]), "+f"(d[2]), "+f"(d[3])
        : "r"(a[0]), "r"(a[1]), "r"(a[2]), "r"(a[3]), "r"(b[0]), "r"(b[1]));
}

__device__ __forceinline__ void mma_bf16(float* d, const unsigned* a, const unsigned* b) {
    asm volatile(
        "mma.sync.aligned.m16n8k16.row.col.f32.bf16.bf16.f32 "
        "{%0,%1,%2,%3}, {%4,%5,%6,%7}, {%8,%9}, {%0,%1,%2,%3};\n"
        : "+f"(d[0]), "+f"(d[1]), "+f"(d[2]), "+f"(d[3])
        : "r"(a[0]), "r"(a[1]), "r"(a[2]), "r"(a[3]), "r"(b[0]), "r"(b[1]));
}

#define STAGES 3
#define APITCH 36
#define BPITCH 136
#define A_STAGE (128*APITCH)
#define B_STAGE (32*BPITCH)
#define GEMM_SMEM (STAGES*(A_STAGE + B_STAGE)*4)   // 107520 bytes
#define BSTG 23040                                  // bf16 stage bytes: 14336 A + 8704 B

struct GJob {
    const float* A; const float* B; const float* bias; void* C;
    int M, N, K, blk_start, outbf, mode;
};
struct GJobs { GJob j[6]; int njobs; };

__global__ __launch_bounds__(256, 2)
void tf32_gemm_multi(GJobs js)
{
    extern __shared__ float sm_[];
    float* Asm = sm_;
    float* Bsm = sm_ + STAGES*A_STAGE;

    int b = blockIdx.x;
    int zi = 0;
    for (int t = 1; t < js.njobs; t++) if (b >= js.j[t].blk_start) zi = t;
    const GJob jb = js.j[zi];
    const int M = jb.M, N = jb.N;
    int local = b - jb.blk_start;
    int ncols = N >> 7;
    int row0 = (local / ncols)*128;
    int col0 = (local % ncols)*128;

    int tid  = threadIdx.x;
    int warp = tid >> 5, lane = tid & 31;
    int wm = warp >> 2, wn = warp & 3;
    int qr = lane >> 2, qc = lane & 3;

    float acc[4][4][4];
    #pragma unroll
    for (int i = 0; i < 4; i++)
        #pragma unroll
        for (int j = 0; j < 4; j++)
            #pragma unroll
            for (int v = 0; v < 4; v++) acc[i][j][v] = 0.f;

    if (jb.mode == 1) {
        // ---- bf16 pipelined path: A bf16 [M][K] row-major, B packed u32 [K/2][N] ----
        const __nv_bfloat16* Ab = (const __nv_bfloat16*)jb.A;
        const unsigned* Bp = (const unsigned*)jb.B;
        const int K = jb.K;
        int nt = K >> 5;
        char* smb = (char*)sm_;

        auto issue_bf = [&](int kt) {
            int s  = kt % STAGES;
            int k0 = kt << 5;
            char* As = smb + s*BSTG;
            char* Bs = smb + s*BSTG + 14336;
            #pragma unroll
            for (int it = 0; it < 2; it++) {
                int id  = tid + it*256;
                int row = id >> 2, kc = id & 3;
                const void* src = Ab + (size_t)(row0+row)*K + k0 + kc*8;
                unsigned dst = (unsigned)__cvta_generic_to_shared(As + row*112 + kc*16);
                int sz = (row0+row < M) ? 16 : 0;
                asm volatile("cp.async.cg.shared.global [%0], [%1], 16, %2;\n"
                             :: "r"(dst), "l"(src), "r"(sz));
            }
            #pragma unroll
            for (int it = 0; it < 2; it++) {
                int id = tid + it*256;
                int k2l = id >> 5, nc = (id & 31)*4;
                const unsigned* src = Bp + (size_t)((k0 >> 1) + k2l)*N + col0 + nc;
                unsigned dst = (unsigned)__cvta_generic_to_shared(Bs + (k2l*136 + nc)*4);
                asm volatile("cp.async.cg.shared.global [%0], [%1], 16, 16;\n"
                             :: "r"(dst), "l"(src));
            }
            asm volatile("cp.async.commit_group;\n");
        };

        auto compute_bf = [&](int s) {
            const char* As = smb + s*BSTG;
            const unsigned* Bs = (const unsigned*)(smb + s*BSTG + 14336);
            #pragma unroll
            for (int ks = 0; ks < 2; ks++) {
                unsigned a[4][4], bfr[4][2];
                #pragma unroll
                for (int mt = 0; mt < 4; mt++) {
                    int m_ = wm*64 + mt*16 + qr;
                    a[mt][0] = *(const unsigned*)(As + m_    *112 + (qc   + ks*8)*4);
                    a[mt][1] = *(const unsigned*)(As + (m_+8)*112 + (qc   + ks*8)*4);
                    a[mt][2] = *(const unsigned*)(As + m_    *112 + (qc+4 + ks*8)*4);
                    a[mt][3] = *(const unsigned*)(As + (m_+8)*112 + (qc+4 + ks*8)*4);
                }
                #pragma unroll
                for (int nt_ = 0; nt_ < 4; nt_++) {
                    int n_ = wn*32 + nt_*8 + qr;
                    bfr[nt_][0] = Bs[(qc   + ks*8)*136 + n_];
                    bfr[nt_][1] = Bs[(qc+4 + ks*8)*136 + n_];
                }
                #pragma unroll
                for (int mt = 0; mt < 4; mt++)
                    #pragma unroll
                    for (int nt_ = 0; nt_ < 4; nt_++)
                        mma_bf16(acc[mt][nt_], a[mt], bfr[nt_]);
            }
        };

        int pre = (nt < STAGES-1) ? nt : (STAGES-1);
        for (int kt = 0; kt < pre; kt++) issue_bf(kt);

        for (int kt = 0; kt < nt; kt++) {
            if (nt - kt - 1 >= 1)
                asm volatile("cp.async.wait_group 1;\n");
            else
                asm volatile("cp.async.wait_group 0;\n");
            __syncthreads();
            compute_bf(kt % STAGES);
            if (kt + STAGES-1 < nt) issue_bf(kt + STAGES-1);
        }
    } else {
        // ---- tf32 cp.async 3-stage pipeline (single sync/iter) ----
        const float* __restrict__ A = jb.A;
        const float* __restrict__ B = jb.B;
        const int K = jb.K;
        int nt = K >> 5;

        auto issue = [&](int kt) {
            int s  = kt % STAGES;
            int k0 = kt << 5;
            float* As = Asm + s*A_STAGE;
            float* Bs = Bsm + s*B_STAGE;
            #pragma unroll
            for (int it = 0; it < 4; it++) {
                int id  = tid + it*256;
                int row = id >> 3;
                int kc  = (id & 7)*4;
                const float* src = A + (size_t)(row0+row)*K + k0 + kc;
                unsigned dst = (unsigned)__cvta_generic_to_shared(As + row*APITCH + kc);
                int sz = (row0+row < M) ? 16 : 0;
                asm volatile("cp.async.cg.shared.global [%0], [%1], 16, %2;\n"
                             :: "r"(dst), "l"(src), "r"(sz));
            }
            #pragma unroll
            for (int it = 0; it < 4; it++) {
                int id = tid + it*256;
                int kr = id >> 5;
                int nc = (id & 31)*4;
                const float* src = B + (size_t)(k0+kr)*N + col0 + nc;
                unsigned dst = (unsigned)__cvta_generic_to_shared(Bs + kr*BPITCH + nc);
                asm volatile("cp.async.cg.shared.global [%0], [%1], 16, 16;\n"
                             :: "r"(dst), "l"(src));
            }
            asm volatile("cp.async.commit_group;\n");
        };

        auto compute = [&](int s) {
            const float* As = Asm + s*A_STAGE;
            const float* Bs = Bsm + s*B_STAGE;
            #pragma unroll
            for (int ks = 0; ks < 4; ks++) {
                int kb = ks*8;
                unsigned a[4][4], bfr[4][2];
                #pragma unroll
                for (int mt = 0; mt < 4; mt++) {
                    int m_ = wm*64 + mt*16 + qr;
                    a[mt][0] = f2tf(As[(size_t)m_     *APITCH + kb+qc  ]);
                    a[mt][1] = f2tf(As[(size_t)(m_+8) *APITCH + kb+qc  ]);
                    a[mt][2] = f2tf(As[(size_t)m_     *APITCH + kb+qc+4]);
                    a[mt][3] = f2tf(As[(size_t)(m_+8) *APITCH + kb+qc+4]);
                }
                #pragma unroll
                for (int nt_ = 0; nt_ < 4; nt_++) {
                    int n_ = wn*32 + nt_*8 + qr;
                    bfr[nt_][0] = f2tf(Bs[(size_t)(kb+qc  )*BPITCH + n_]);
                    bfr[nt_][1] = f2tf(Bs[(size_t)(kb+qc+4)*BPITCH + n_]);
                }
                #pragma unroll
                for (int mt = 0; mt < 4; mt++)
                    #pragma unroll
                    for (int nt_ = 0; nt_ < 4; nt_++)
                        mma_tf32(acc[mt][nt_], a[mt], bfr[nt_]);
            }
        };

        int pre = (nt < STAGES-1) ? nt : (STAGES-1);
        for (int kt = 0; kt < pre; kt++) issue(kt);

        for (int kt = 0; kt < nt; kt++) {
            if (nt - kt - 1 >= 1)
                asm volatile("cp.async.wait_group 1;\n");
            else
                asm volatile("cp.async.wait_group 0;\n");
            __syncthreads();
            compute(kt % STAGES);
            if (kt + STAGES-1 < nt) issue(kt + STAGES-1);
        }
    }

    // ---- common epilogue ----
    const float* bias = jb.bias;
    #pragma unroll
    for (int mt = 0; mt < 4; mt++) {
        int r  = row0 + wm*64 + mt*16 + qr;
        int r2 = r + 8;
        #pragma unroll
        for (int nt_ = 0; nt_ < 4; nt_++) {
            int c = col0 + wn*32 + nt_*8 + qc*2;
            float b0 = bias[c], b1 = bias[c+1];
            if (jb.outbf) {
                __nv_bfloat16* Cb = (__nv_bfloat16*)jb.C;
                if (r  < M) {
                    __nv_bfloat162 h = __floats2bfloat162_rn(acc[mt][nt_][0] + b0, acc[mt][nt_][1] + b1);
                    __stcs((unsigned*)(Cb + (size_t)r*N + c), *reinterpret_cast<unsigned*>(&h));
                }
                if (r2 < M) {
                    __nv_bfloat162 h = __floats2bfloat162_rn(acc[mt][nt_][2] + b0, acc[mt][nt_][3] + b1);
                    __stcs((unsigned*)(Cb + (size_t)r2*N + c), *reinterpret_cast<unsigned*>(&h));
                }
            } else {
                float* C = (float*)jb.C;
                if (r  < M) {
                    C[(size_t)r *N + c]   = acc[mt][nt_][0] + b0;
                    C[(size_t)r *N + c+1] = acc[mt][nt_][1] + b1;
                }
                if (r2 < M) {
                    C[(size_t)r2*N + c]   = acc[mt][nt_][2] + b0;
                    C[(size_t)r2*N + c+1] = acc[mt][nt_][3] + b1;
                }
            }
        }
    }
}

// ---------------- fused GATv2 aggregation: one warp per (node, head) ----------------
// EPI: 0 = layer 2: block merge of 4 heads (mean) + bias + ELU -> g_H2 (+bf16 copy)
//      1 = +bias +residual(g_H1) +leaky_relu, write g_H1 (+bf16 copy)
//      2 = layer 3 (H=1): +bias +ELU, then FUSED classifier head -> out
template<int D, int H, int EPI>
__global__ __launch_bounds__(256)
void gat_node(const __nv_bfloat16* __restrict__ EW, const float* __restrict__ att,
              const float* __restrict__ bo,
              const float* __restrict__ Wc1, const float* __restrict__ bc1,
              const float* __restrict__ Wc2, const float* __restrict__ bc2,
              float* __restrict__ out)
{
    int warp = (blockIdx.x*blockDim.x + threadIdx.x) >> 5;
    int lane = threadIdx.x & 31;
    if (warp >= N_NODES*H) return;
    int d = warp / H, h = warp % H;
    const int cbase = h*128 + lane*4;

    float4 a4 = *(const float4*)(att + h*128 + lane*4);
    float4 xr = *(const float4*)(g_XR + (size_t)d*D + cbase);

    float m0 = -INFINITY, z0 = 0.f, A00 = 0.f, A01 = 0.f, A02 = 0.f, A03 = 0.f;
    float m1 = -INFINITY, z1 = 0.f, A10 = 0.f, A11 = 0.f, A12 = 0.f, A13 = 0.f;

    int start = g_rowstart[d], end = g_rowstart[d+1];
    int pos = start;

    for (; pos + 2 <= end; pos += 2) {
        int sa = g_csr_src[pos];
        int sb = g_csr_src[pos+1];
        uint2 ra = __ldcs((const uint2*)(EW + (size_t)pos    *D + cbase));
        uint2 rb = __ldcs((const uint2*)(EW + (size_t)(pos+1)*D + cbase));
        float4 xla = *(const float4*)(g_XL + (size_t)sa*D + cbase);
        float4 xlb = *(const float4*)(g_XL + (size_t)sb*D + cbase);

        float2 wa01 = __bfloat1622float2(*reinterpret_cast<const __nv_bfloat162*>(&ra.x));
        float2 wa23 = __bfloat1622float2(*reinterpret_cast<const __nv_bfloat162*>(&ra.y));
        float2 wb01 = __bfloat1622float2(*reinterpret_cast<const __nv_bfloat162*>(&rb.x));
        float2 wb23 = __bfloat1622float2(*reinterpret_cast<const __nv_bfloat162*>(&rb.y));

        float qa0 = xla.x + xr.x + wa01.x;
        float qa1 = xla.y + xr.y + wa01.y;
        float qa2 = xla.z + xr.z + wa23.x;
        float qa3 = xla.w + xr.w + wa23.y;
        float qb0 = xlb.x + xr.x + wb01.x;
        float qb1 = xlb.y + xr.y + wb01.y;
        float qb2 = xlb.z + xr.z + wb23.x;
        float qb3 = xlb.w + xr.w + wb23.y;
        qa0 = (qa0 > 0.f) ? qa0 : 0.2f*qa0;
        qa1 = (qa1 > 0.f) ? qa1 : 0.2f*qa1;
        qa2 = (qa2 > 0.f) ? qa2 : 0.2f*qa2;
        qa3 = (qa3 > 0.f) ? qa3 : 0.2f*qa3;
        qb0 = (qb0 > 0.f) ? qb0 : 0.2f*qb0;
        qb1 = (qb1 > 0.f) ? qb1 : 0.2f*qb1;
        qb2 = (qb2 > 0.f) ? qb2 : 0.2f*qb2;
        qb3 = (qb3 > 0.f) ? qb3 : 0.2f*qb3;

        float pa = a4.x*qa0 + a4.y*qa1 + a4.z*qa2 + a4.w*qa3;
        float pb = a4.x*qb0 + a4.y*qb1 + a4.z*qb2 + a4.w*qb3;
        #pragma unroll
        for (int off = 16; off > 0; off >>= 1) {
            pa += __shfl_xor_sync(0xffffffffu, pa, off);
            pb += __shfl_xor_sync(0xffffffffu, pb, off);
        }

        float nm0 = fmaxf(m0, pa);
        float sc0 = __expf(m0 - nm0);
        float w0  = __expf(pa - nm0);
        z0  = z0*sc0 + w0;
        A00 = A00*sc0 + w0*xla.x;
        A01 = A01*sc0 + w0*xla.y;
        A02 = A02*sc0 + w0*xla.z;
        A03 = A03*sc0 + w0*xla.w;
        m0 = nm0;

        float nm1 = fmaxf(m1, pb);
        float sc1 = __expf(m1 - nm1);
        float w1  = __expf(pb - nm1);
        z1  = z1*sc1 + w1;
        A10 = A10*sc1 + w1*xlb.x;
        A11 = A11*sc1 + w1*xlb.y;
        A12 = A12*sc1 + w1*xlb.z;
        A13 = A13*sc1 + w1*xlb.w;
        m1 = nm1;
    }

    if (pos < end) {
        int s_ = g_csr_src[pos];
        uint2 r_ = __ldcs((const uint2*)(EW + (size_t)pos*D + cbase));
        float4 xl = *(const float4*)(g_XL + (size_t)s_*D + cbase);
        float2 w01 = __bfloat1622float2(*reinterpret_cast<const __nv_bfloat162*>(&r_.x));
        float2 w23 = __bfloat1622float2(*reinterpret_cast<const __nv_bfloat162*>(&r_.y));
        float q0 = xl.x + xr.x + w01.x;
        float q1 = xl.y + xr.y + w01.y;
        float q2 = xl.z + xr.z + w23.x;
        float q3 = xl.w + xr.w + w23.y;
        q0 = (q0 > 0.f) ? q0 : 0.2f*q0;
        q1 = (q1 > 0.f) ? q1 : 0.2f*q1;
        q2 = (q2 > 0.f) ? q2 : 0.2f*q2;
        q3 = (q3 > 0.f) ? q3 : 0.2f*q3;
        float p = a4.x*q0 + a4.y*q1 + a4.z*q2 + a4.w*q3;
        #pragma unroll
        for (int off = 16; off > 0; off >>= 1)
            p += __shfl_xor_sync(0xffffffffu, p, off);
        float nm0 = fmaxf(m0, p);
        float sc0 = __expf(m0 - nm0);
        float w0  = __expf(p - nm0);
        z0  = z0*sc0 + w0;
        A00 = A00*sc0 + w0*xl.x;
        A01 = A01*sc0 + w0*xl.y;
        A02 = A02*sc0 + w0*xl.z;
        A03 = A03*sc0 + w0*xl.w;
        m0 = nm0;
    }

    float M_ = fmaxf(m0, m1);
    float s0 = __expf(m0 - M_);
    float s1 = __expf(m1 - M_);
    float z  = z0*s0 + z1*s1;
    float o0 = A00*s0 + A10*s1;
    float o1 = A01*s0 + A11*s1;
    float o2 = A02*s0 + A12*s1;
    float o3 = A03*s0 + A13*s1;

    float inv = 1.0f / (z + 1e-16f);
    o0 *= inv; o1 *= inv; o2 *= inv; o3 *= inv;

    if (EPI == 0) {
        __shared__ float sm[8][132];
        int wid = threadIdx.x >> 5;
        sm[wid][lane*4+0] = o0;
        sm[wid][lane*4+1] = o1;
        sm[wid][lane*4+2] = o2;
        sm[wid][lane*4+3] = o3;
        __syncthreads();
        int t = threadIdx.x;
        int slot = t >> 7, c = t & 127;
        int dd = blockIdx.x*2 + slot;
        float v = 0.25f*(sm[slot*4+0][c] + sm[slot*4+1][c] +
                         sm[slot*4+2][c] + sm[slot*4+3][c]) + bo[c];
        v = (v > 0.f) ? v : expm1f(v);
        g_H2[dd*128 + c]  = v;
        g_H2B[dd*128 + c] = __float2bfloat16_rn(v);
    } else if (EPI == 1) {
        float4 b4  = *(const float4*)(bo + cbase);
        float4 res = *(const float4*)(g_H1 + (size_t)d*1024 + cbase);
        float v0 = o0 + b4.x + res.x;
        float v1 = o1 + b4.y + res.y;
        float v2 = o2 + b4.z + res.z;
        float v3 = o3 + b4.w + res.w;
        v0 = (v0 > 0.f) ? v0 : 0.2f*v0;
        v1 = (v1 > 0.f) ? v1 : 0.2f*v1;
        v2 = (v2 > 0.f) ? v2 : 0.2f*v2;
        v3 = (v3 > 0.f) ? v3 : 0.2f*v3;
        *(float4*)(g_H1 + (size_t)d*1024 + cbase) = make_float4(v0, v1, v2, v3);
        __nv_bfloat162 h01 = __floats2bfloat162_rn(v0, v1);
        __nv_bfloat162 h23 = __floats2bfloat162_rn(v2, v3);
        uint2 u = make_uint2(*reinterpret_cast<unsigned*>(&h01),
                             *reinterpret_cast<unsigned*>(&h23));
        *(uint2*)(g_H1B + (size_t)d*1024 + cbase) = u;
    } else {
        __shared__ float sh3[8][132];
        __shared__ float shc[8][64];
        float4 b4 = *(const float4*)(bo + cbase);
        float v0 = o0 + b4.x;
        float v1 = o1 + b4.y;
        float v2 = o2 + b4.z;
        float v3 = o3 + b4.w;
        v0 = (v0 > 0.f) ? v0 : expm1f(v0);
        v1 = (v1 > 0.f) ? v1 : expm1f(v1);
        v2 = (v2 > 0.f) ? v2 : expm1f(v2);
        v3 = (v3 > 0.f) ? v3 : expm1f(v3);
        int wid = threadIdx.x >> 5;
        sh3[wid][lane*4+0] = v0;
        sh3[wid][lane*4+1] = v1;
        sh3[wid][lane*4+2] = v2;
        sh3[wid][lane*4+3] = v3;
        __syncthreads();
        {
            int nd = wid;
            int j0 = lane*2;
            float t0 = bc1[j0], t1 = bc1[j0+1];
            #pragma unroll 4
            for (int c = 0; c < 128; c++) {
                float hv = sh3[nd][c];
                t0 = fmaf(hv, Wc1[c*64 + j0],     t0);
                t1 = fmaf(hv, Wc1[c*64 + j0 + 1], t1);
            }
            t0 = (t0 > 0.f) ? t0 : expm1f(t0);
            t1 = (t1 > 0.f) ? t1 : expm1f(t1);
            shc[nd][j0]   = t0;
            shc[nd][j0+1] = t1;
        }
        __syncthreads();
        if (lane < 3) {
            int nd = wid;
            float s = bc2[lane];
            #pragma unroll 8
            for (int k = 0; k < 64; k++)
                s = fmaf(shc[nd][k], Wc2[k*3 + lane], s);
            out[(blockIdx.x*8 + nd)*3 + lane] = s;
        }
    }
}

// ---------------- launch ----------------
extern "C" void kernel_launch(void* const* d_in, const int* in_sizes, int n_in,
                              void* d_out, int out_size)
{
    const float* x    = (const float*)d_in[0];
    const int*   ei   = (const int*)  d_in[1];
    const float* ea   = (const float*)d_in[2];
    const float* Wl1  = (const float*)d_in[3];
    const float* bl1  = (const float*)d_in[4];
    const float* Wr1  = (const float*)d_in[5];
    const float* br1  = (const float*)d_in[6];
    const float* We1  = (const float*)d_in[7];
    const float* att1 = (const float*)d_in[8];
    const float* bo1  = (const float*)d_in[9];
    const float* Wl2  = (const float*)d_in[10];
    const float* bl2  = (const float*)d_in[11];
    const float* Wr2  = (const float*)d_in[12];
    const float* br2  = (const float*)d_in[13];
    const float* We2  = (const float*)d_in[14];
    const float* att2 = (const float*)d_in[15];
    const float* bo2  = (const float*)d_in[16];
    const float* Wl3  = (const float*)d_in[17];
    const float* bl3  = (const float*)d_in[18];
    const float* Wr3  = (const float*)d_in[19];
    const float* br3  = (const float*)d_in[20];
    const float* We3  = (const float*)d_in[21];
    const float* att3 = (const float*)d_in[22];
    const float* bo3  = (const float*)d_in[23];
    const float* Wres = (const float*)d_in[24];
    const float* bres = (const float*)d_in[25];
    const float* Wc1  = (const float*)d_in[26];
    const float* bc1  = (const float*)d_in[27];
    const float* Wc2  = (const float*)d_in[28];
    const float* bc2  = (const float*)d_in[29];
    float* out = (float*)d_out;

    void *pXL, *pXR, *pH1, *pH2, *pXBF, *pH1B, *pH2B, *pEAFP, *pZB;
    void *pWeP1, *pWeP2, *pWeP3, *pWrP1, *pWrP2, *pWrP3, *pEW1, *pEW2, *pEW3;
    cudaGetSymbolAddress(&pXL,   g_XL);
    cudaGetSymbolAddress(&pXR,   g_XR);
    cudaGetSymbolAddress(&pH1,   g_H1);
    cudaGetSymbolAddress(&pH2,   g_H2);
    cudaGetSymbolAddress(&pXBF,  g_XBF);
    cudaGetSymbolAddress(&pH1B,  g_H1B);
    cudaGetSymbolAddress(&pH2B,  g_H2B);
    cudaGetSymbolAddress(&pEAFP, g_EAFP);
    cudaGetSymbolAddress(&pWeP1, g_WeP1);
    cudaGetSymbolAddress(&pWeP2, g_WeP2);
    cudaGetSymbolAddress(&pWeP3, g_WeP3);
    cudaGetSymbolAddress(&pWrP1, g_WrP1);
    cudaGetSymbolAddress(&pWrP2, g_WrP2);
    cudaGetSymbolAddress(&pWrP3, g_WrP3);
    cudaGetSymbolAddress(&pEW1,  g_EW1);
    cudaGetSymbolAddress(&pEW2,  g_EW2);
    cudaGetSymbolAddress(&pEW3,  g_EW3);
    cudaGetSymbolAddress(&pZB,   g_zbias);

    cudaFuncSetAttribute(tf32_gemm_multi, cudaFuncAttributeMaxDynamicSharedMemorySize, GEMM_SMEM);

    // graph structure + conversions (rebuilt every call: deterministic work)
    ea_mean_zero_k<<<32, 256>>>(ea);
    pack_k<<<dim3(256, 7), 256>>>(We1, We2, We3, Wr1, Wr2, Wr3, x);
    count_deg_k<<<(ETOT+255)/256, 256>>>(ei);
    scan_deg_k<<<1, 1024>>>();
    scatter_fill_k<<<(ETOT+255)/256, 256>>>(ei, ea);

    const int MT = (N_NODES + 127)/128;   // 79
    const int ET = (ETOT + 127)/128;      // 1329

    // ---- mega-launch: XL1/RES (tf32) + XR1 (bf16) + EW1/2/3 (bf16) ----
    {
        GJobs js;
        const float* eaf = (const float*)pEAFP;
        const float* zb  = (const float*)pZB;
        js.j[0] = { x,                   Wl1,  bl1,  pXL,  N_NODES, 1024, 128, 0,      0, 0 };
        js.j[1] = { x,                   Wres, bres, pH1,  N_NODES, 1024, 128, MT*8,   0, 0 };
        js.j[2] = { (const float*)pXBF,  (const float*)pWrP1, br1, pXR, N_NODES, 1024, 128, 2*MT*8, 0, 1 };
        js.j[3] = { eaf, (const float*)pWeP1, zb, pEW1, ETOT, 1024, 32, 3*MT*8,          1, 1 };
        js.j[4] = { eaf, (const float*)pWeP2, zb, pEW2, ETOT, 512,  32, 3*MT*8 + ET*8,   1, 1 };
        js.j[5] = { eaf, (const float*)pWeP3, zb, pEW3, ETOT, 128,  32, 3*MT*8 + ET*12,  1, 1 };
        js.njobs = 6;
        int nblk = 3*MT*8 + ET*13;
        tf32_gemm_multi<<<nblk, 256, GEMM_SMEM>>>(js);
    }
    gat_node<1024,8,1><<<(N_NODES*8*32)/256, 256>>>((const __nv_bfloat16*)pEW1, att1, bo1,
                                                    nullptr, nullptr, nullptr, nullptr, nullptr);

    // ---- layer 2: XL (tf32, fp32 H1) + XR (bf16, H1B) ----
    {
        GJobs js;
        js.j[0] = { (const float*)pH1,  Wl2, bl2, pXL, N_NODES, 512, 1024, 0,    0, 0 };
        js.j[1] = { (const float*)pH1B, (const float*)pWrP2, br2, pXR, N_NODES, 512, 1024, MT*4, 0, 1 };
        js.j[2] = js.j[1]; js.j[3] = js.j[1]; js.j[4] = js.j[1]; js.j[5] = js.j[1];
        js.njobs = 2;
        tf32_gemm_multi<<<2*MT*4, 256, GEMM_SMEM>>>(js);
    }
    gat_node<512,4,0><<<(N_NODES*4*32)/256, 256>>>((const __nv_bfloat16*)pEW2, att2, bo2,
                                                   nullptr, nullptr, nullptr, nullptr, nullptr);

    // ---- layer 3: XL (tf32) + XR (bf16) ----
    {
        GJobs js;
        js.j[0] = { (const float*)pH2,  Wl3, bl3, pXL, N_NODES, 128, 128, 0,  0, 0 };
        js.j[1] = { (const float*)pH2B, (const float*)pWrP3, br3, pXR, N_NODES, 128, 128, MT, 0, 1 };
        js.j[2] = js.j[1]; js.j[3] = js.j[1]; js.j[4] = js.j[1]; js.j[5] = js.j[1];
        js.njobs = 2;
        tf32_gemm_multi<<<2*MT, 256, GEMM_SMEM>>>(js);
    }
    gat_node<128,1,2><<<(N_NODES*1*32)/256, 256>>>((const __nv_bfloat16*)pEW3, att3, bo3,
                                                   Wc1, bc1, Wc2, bc2, out);
}